// round 13
// baseline (speedup 1.0000x reference)
#include <cuda_runtime.h>

#define DD 64
#define HH 512
#define WW 512
#define W4 (WW / 4)
#define THRESH 0.5f

// 64 MB scratch (device global, allocation-free rule). Convention:
//   stored value = +whmax  if raw center == 9x9 WH-window max (flag set)
//                = -whmax  otherwise.
__device__ float4 g_tmp[(size_t)DD * HH * W4];

#define TH1 24   // H rows per k1 block -> 32 trips
#define DSEG 16  // D outputs per thread in k2 -> 24 trips

__device__ __forceinline__ float4 vmax4(float4 a, float4 b) {
    return make_float4(fmaxf(a.x, b.x), fmaxf(a.y, b.y),
                       fmaxf(a.z, b.z), fmaxf(a.w, b.w));
}
__device__ __forceinline__ float4 vabs4(float4 a) {
    return make_float4(fabsf(a.x), fabsf(a.y), fabsf(a.z), fabsf(a.w));
}

// ---------------------------------------------------------------------------
// k1 body: 9-tap W max (tree) + 9-tap H max via van Herk (in-place ring
// suffix at trip%9==8, running prefix P). out[o] = max(S[o-4], P).
// Flag (whmax == raw center, center re-read at emit -> L1 hit) packed as
// sign via negate-select. IB=true: no H bounds checks. Threshold deferred.
// ---------------------------------------------------------------------------
template <bool IB>
__device__ __forceinline__ void wh_body(const float4* __restrict__ base,
                                        float4* __restrict__ tmpb,
                                        int h0, int t) {
    const float4 z4 = make_float4(0.f, 0.f, 0.f, 0.f);
    float4 ring[9];
    float4 P = z4;

#pragma unroll
    for (int hh = 0; hh < TH1 + 8; hh++) {       // 32 trips, fully unrolled
        const int hi = h0 - 4 + hh;
        float4 L, M, R;
        if (IB) {
            const float4* row = base + (size_t)hi * W4;
            L = (t > 0)      ? row[t - 1] : z4;
            M = row[t];
            R = (t < W4 - 1) ? row[t + 1] : z4;
        } else {
            const bool rowok = (hi >= 0) & (hi < HH);
            const float4* row = base + (size_t)hi * W4;
            L = (rowok && t > 0)      ? row[t - 1] : z4;
            M = rowok                 ? row[t]     : z4;
            R = (rowok && t < W4 - 1) ? row[t + 1] : z4;
        }

        // 9-tap W max: a0..a11 = L.xyzw M.xyzw R.xyzw, out_i = max(a[i..i+8])
        float c  = fmaxf(fmaxf(fmaxf(L.w, M.x), fmaxf(M.y, M.z)),
                         fmaxf(M.w, R.x));       // max(a3..a8)
        float u1 = fmaxf(L.y, L.z);
        float u2 = fmaxf(R.y, R.z);
        float4 y;
        y.x = fmaxf(fmaxf(c, L.x), u1);
        y.y = fmaxf(fmaxf(c, R.y), u1);
        y.z = fmaxf(fmaxf(c, L.z), u2);
        y.w = fmaxf(fmaxf(c, R.w), u2);

        ring[hh % 9] = y;                        // static index (full unroll)
        P = (hh % 9 == 0) ? y : vmax4(P, y);     // prefix within segment

        if (hh % 9 == 8) {                       // segment end: in-place suffix
#pragma unroll
            for (int i = 7; i >= 0; i--) ring[i] = vmax4(ring[i], ring[i + 1]);
        }

        const int ho = h0 + hh - 8;              // output row (cursor-4)
        if (hh >= 8 && (IB || ho < HH)) {
            float4 m = vmax4(ring[(hh - 8) % 9], P);
            const float4 cen = base[(size_t)ho * W4 + t];   // L1 hit
            float4 o;                // +m if center is WH-window max, else -m
            o.x = (m.x == cen.x) ? m.x : -m.x;
            o.y = (m.y == cen.y) ? m.y : -m.y;
            o.z = (m.z == cen.z) ? m.z : -m.z;
            o.w = (m.w == cen.w) ? m.w : -m.w;
            tmpb[(size_t)ho * W4 + t] = o;
        }
    }
}

// Interior: h0 = 24 + 24*by, by = 0..19 (rows 24..503; all hi in [20,507]).
// Separate __global__ so ptxas regallocs it independently of the guarded path.
__global__ void __launch_bounds__(128, 6) k_wh_int(const float4* __restrict__ in) {
    const int d = blockIdx.z;
    wh_body<true>(in + (size_t)d * HH * W4, g_tmp + (size_t)d * HH * W4,
                  TH1 + (int)blockIdx.y * TH1, threadIdx.x);
}

// Boundary: by=0 -> h0=0 (rows 0..23), by=1 -> h0=504 (rows 504..511 guarded).
__global__ void __launch_bounds__(128) k_wh_bnd(const float4* __restrict__ in) {
    const int d = blockIdx.z;
    wh_body<false>(in + (size_t)d * HH * W4, g_tmp + (size_t)d * HH * W4,
                   (blockIdx.y == 0) ? 0 : (HH - 8), threadIdx.x);
}

// ---------------------------------------------------------------------------
// k2: 9-tap D max over |tmp| via van Herk. Gate: out = m if (m > 0.5 &&
// cv == m) else 0, cv = signed tmp at center plane (re-read, L1 hit).
// cv == m > 0.5 implies flag set AND center == D-window max.
// grid: (512, 4), block 128, DSEG=16 -> 24 trips. minBlocks=8 caps regs.
// ---------------------------------------------------------------------------
__global__ void __launch_bounds__(128, 8) k_d(float4* __restrict__ out) {
    const size_t col   = (size_t)blockIdx.x * 128 + threadIdx.x;
    const int    d0    = blockIdx.y * DSEG;
    const size_t slice = (size_t)HH * W4;

    const float4 z4 = make_float4(0.f, 0.f, 0.f, 0.f);
    float4 ring[9];
    float4 P = z4;

#pragma unroll
    for (int di = 0; di < DSEG + 8; di++) {      // 24 trips, fully unrolled
        const int p = d0 + di - 4;               // cursor plane
        float4 v = z4;
        if ((unsigned)p < DD) v = g_tmp[(size_t)p * slice + col];
        float4 a = vabs4(v);

        ring[di % 9] = a;
        P = (di % 9 == 0) ? a : vmax4(P, a);

        if (di % 9 == 8) {                       // di = 8, 17
#pragma unroll
            for (int i = 7; i >= 0; i--) ring[i] = vmax4(ring[i], ring[i + 1]);
        }

        const int o = di - 8;                    // output plane offset
        if (o >= 0) {
            float4 m = vmax4(ring[(di - 8) % 9], P);
            const float4 cv = g_tmp[(size_t)(d0 + o) * slice + col];  // L1 hit
            float4 ov;
            ov.x = (m.x > THRESH && cv.x == m.x) ? m.x : 0.f;
            ov.y = (m.y > THRESH && cv.y == m.y) ? m.y : 0.f;
            ov.z = (m.z > THRESH && cv.z == m.z) ? m.z : 0.f;
            ov.w = (m.w > THRESH && cv.w == m.w) ? m.w : 0.f;
            out[(size_t)(d0 + o) * slice + col] = ov;
        }
    }
}

extern "C" void kernel_launch(void* const* d_in, const int* in_sizes, int n_in,
                              void* d_out, int out_size) {
    const float4* in  = (const float4*)d_in[0];
    float4*       out = (float4*)d_out;

    dim3 gb(1, 2, DD);                   // 128 blocks (guarded edges)
    k_wh_bnd<<<gb, 128>>>(in);
    dim3 gi(1, 20, DD);                  // 1280 blocks (unguarded interior)
    k_wh_int<<<gi, 128>>>(in);

    dim3 g2((HH * W4) / 128, DD / DSEG); // (512, 4) = 2048 blocks
    k_d<<<g2, 128>>>(out);
}

// round 14
// speedup vs baseline: 1.2667x; 1.2667x over previous
#include <cuda_runtime.h>

#define DD 64
#define HH 512
#define WW 512
#define W4 (WW / 4)
#define THRESH 0.5f

// 64 MB scratch (device global, allocation-free rule). Convention:
//   stored value = +whmax  if raw center == 9x9 WH-window max (flag set)
//                = -whmax  otherwise.
__device__ float4 g_tmp[(size_t)DD * HH * W4];

#define TH1 16   // H rows per k1 block -> 24 trips; 32 y-blocks cover 512 exactly
#define DSEG 16  // D outputs per thread in k2 -> 24 trips

__device__ __forceinline__ float4 vmax4(float4 a, float4 b) {
    return make_float4(fmaxf(a.x, b.x), fmaxf(a.y, b.y),
                       fmaxf(a.z, b.z), fmaxf(a.w, b.w));
}
__device__ __forceinline__ float4 vabs4(float4 a) {
    return make_float4(fabsf(a.x), fabsf(a.y), fabsf(a.z), fabsf(a.w));
}
__device__ __forceinline__ int iclamp(int v, int lo, int hi) {
    return min(max(v, lo), hi);
}

// ---------------------------------------------------------------------------
// k1: 9-tap W max (tree, L/R float4 clamped at row ends) + 9-tap H max via
// van Herk (in-place ring suffix at trip%9==8, running prefix P).
// CLAMP-TO-EDGE padding is exact for max-pool: a clamped duplicate row is
// always already inside the window it pads. -> no bounds predicates at all.
// Flag (whmax == raw center, center re-read at emit, L1 hit) packed as sign.
// Threshold deferred (raw >= 0). grid (1, 32, 64), block 128.
// ---------------------------------------------------------------------------
__global__ void __launch_bounds__(128) k_wh(const float4* __restrict__ in) {
    const int t  = threadIdx.x;
    const int h0 = blockIdx.y * TH1;
    const int d  = blockIdx.z;
    const float4* base = in    + (size_t)d * HH * W4;
    float4*       tmpb = g_tmp + (size_t)d * HH * W4;

    const int tL = max(t - 1, 0);          // clamped once, loop-invariant
    const int tR = min(t + 1, W4 - 1);

    float4 ring[9];
    float4 P;

#pragma unroll
    for (int hh = 0; hh < TH1 + 8; hh++) {       // 24 trips, fully unrolled
        const int hc = iclamp(h0 - 4 + hh, 0, HH - 1);   // exact edge padding
        const float4* row = base + (size_t)hc * W4;
        const float4 L = row[tL];
        const float4 M = row[t];
        const float4 R = row[tR];

        // 9-tap W max: a0..a11 = L.xyzw M.xyzw R.xyzw, out_i = max(a[i..i+8])
        float c  = fmaxf(fmaxf(fmaxf(L.w, M.x), fmaxf(M.y, M.z)),
                         fmaxf(M.w, R.x));       // max(a3..a8)
        float u1 = fmaxf(L.y, L.z);
        float u2 = fmaxf(R.y, R.z);
        float4 y;
        y.x = fmaxf(fmaxf(c, L.x), u1);
        y.y = fmaxf(fmaxf(c, R.y), u1);
        y.z = fmaxf(fmaxf(c, L.z), u2);
        y.w = fmaxf(fmaxf(c, R.w), u2);

        ring[hh % 9] = y;                        // static index (full unroll)
        P = (hh % 9 == 0) ? y : vmax4(P, y);     // prefix within segment

        if (hh % 9 == 8) {                       // segment end: in-place suffix
#pragma unroll
            for (int i = 7; i >= 0; i--) ring[i] = vmax4(ring[i], ring[i + 1]);
        }

        if (hh >= 8) {                           // output row always valid
            const int ho = h0 + hh - 8;
            float4 m = vmax4(ring[(hh - 8) % 9], P);
            const float4 cen = base[(size_t)ho * W4 + t];   // L1 hit
            float4 o;                // +m if center is WH-window max, else -m
            o.x = (m.x == cen.x) ? m.x : -m.x;
            o.y = (m.y == cen.y) ? m.y : -m.y;
            o.z = (m.z == cen.z) ? m.z : -m.z;
            o.w = (m.w == cen.w) ? m.w : -m.w;
            tmpb[(size_t)ho * W4 + t] = o;
        }
    }
}

// ---------------------------------------------------------------------------
// k2: 9-tap D max over |tmp| via van Herk, clamp-to-edge D padding (exact),
// unconditional loads. Gate: out = m if (m > 0.5 && cv == m) else 0, where
// cv = signed tmp at center plane (re-read, L1 hit); cv == m > 0.5 implies
// flag set AND center == D-window max. grid (512, 4), block 128.
// ---------------------------------------------------------------------------
__global__ void __launch_bounds__(128) k_d(float4* __restrict__ out) {
    const size_t col   = (size_t)blockIdx.x * 128 + threadIdx.x;
    const int    d0    = blockIdx.y * DSEG;
    const size_t slice = (size_t)HH * W4;

    float4 ring[9];
    float4 P;

#pragma unroll
    for (int di = 0; di < DSEG + 8; di++) {      // 24 trips, fully unrolled
        const int pc = iclamp(d0 + di - 4, 0, DD - 1);   // exact edge padding
        const float4 a = vabs4(g_tmp[(size_t)pc * slice + col]);

        ring[di % 9] = a;
        P = (di % 9 == 0) ? a : vmax4(P, a);

        if (di % 9 == 8) {                       // di = 8, 17
#pragma unroll
            for (int i = 7; i >= 0; i--) ring[i] = vmax4(ring[i], ring[i + 1]);
        }

        if (di >= 8) {
            const int o = d0 + di - 8;           // always in [d0, d0+DSEG)
            float4 m = vmax4(ring[(di - 8) % 9], P);
            const float4 cv = g_tmp[(size_t)o * slice + col];   // L1 hit
            float4 ov;
            ov.x = (m.x > THRESH && cv.x == m.x) ? m.x : 0.f;
            ov.y = (m.y > THRESH && cv.y == m.y) ? m.y : 0.f;
            ov.z = (m.z > THRESH && cv.z == m.z) ? m.z : 0.f;
            ov.w = (m.w > THRESH && cv.w == m.w) ? m.w : 0.f;
            out[(size_t)o * slice + col] = ov;
        }
    }
}

extern "C" void kernel_launch(void* const* d_in, const int* in_sizes, int n_in,
                              void* d_out, int out_size) {
    const float4* in  = (const float4*)d_in[0];
    float4*       out = (float4*)d_out;

    dim3 g1(1, HH / TH1, DD);            // (1, 32, 64) = 2048 blocks
    k_wh<<<g1, 128>>>(in);

    dim3 g2((HH * W4) / 128, DD / DSEG); // (512, 4) = 2048 blocks
    k_d<<<g2, 128>>>(out);
}